// round 3
// baseline (speedup 1.0000x reference)
#include <cuda_runtime.h>

#define N_NODES 100000
#define N_EDGES 1600000
#define IN_DIM  12
#define HID     128
#define OUT_DIM 13
#define WPB     8      // warps (=nodes) per block

// ---------------- scratch (static device globals; no allocation) ----------------
// idx layout: [0 .. N_NODES]   rowstart (N_NODES+1 ints)
//             [N_NODES+1 ..]   cursor   (N_NODES ints)
__device__ int   g_idx[2 * N_NODES + 1];
__device__ int   g_csr_src[N_EDGES];
__device__ float g_h[2 * (size_t)N_NODES * HID];   // [0]=h1, [N*HID]=h2

// ---------------- CSR construction ----------------
__global__ void zero_deg_kernel() {
    int i = blockIdx.x * blockDim.x + threadIdx.x;
    if (i < N_NODES) g_idx[i] = 0;           // use rowstart slots as degree counters
}

__global__ void hist_kernel(const int* __restrict__ ei) {
    int e = blockIdx.x * blockDim.x + threadIdx.x;
    if (e < N_EDGES) atomicAdd(&g_idx[__ldg(&ei[N_EDGES + e])], 1);  // dst row
}

// one-block exclusive scan: g_idx[0..N) (degrees) -> rowstart in place, cursor copy
__global__ void scan_kernel() {
    const int T = 1024;
    int t = threadIdx.x;
    const int per = (N_NODES + T - 1) / T;
    int beg = t * per;
    int end = beg + per; if (end > N_NODES) end = N_NODES;
    if (beg > N_NODES) beg = N_NODES;

    int deg_local[98];
    int s = 0, cnt = end - beg;
    for (int i = 0; i < cnt; i++) { deg_local[i] = g_idx[beg + i]; s += deg_local[i]; }

    __shared__ int sh[T];
    sh[t] = s;
    __syncthreads();
    for (int off = 1; off < T; off <<= 1) {
        int v = (t >= off) ? sh[t - off] : 0;
        __syncthreads();
        sh[t] += v;
        __syncthreads();
    }
    int run = sh[t] - s;  // exclusive prefix
    for (int i = 0; i < cnt; i++) {
        g_idx[beg + i]               = run;   // rowstart
        g_idx[N_NODES + 1 + beg + i] = run;   // cursor
        run += deg_local[i];
    }
    if (t == 0) g_idx[N_NODES] = sh[T - 1];
}

__global__ void scatter_kernel(const int* __restrict__ ei) {
    int e = blockIdx.x * blockDim.x + threadIdx.x;
    if (e < N_EDGES) {
        int dst = __ldg(&ei[N_EDGES + e]);
        int pos = atomicAdd(&g_idx[N_NODES + 1 + dst], 1);
        g_csr_src[pos] = __ldg(&ei[e]);   // src
    }
}

// ---------------- layer 0: agg(x, 12-dim) + FC(12->128) + relu -> h1 ----------------
__global__ void layer0_kernel(const float* __restrict__ x,
                              const float* __restrict__ Wl,
                              const float* __restrict__ Wr,
                              const float* __restrict__ b) {
    __shared__ float sh[WPB][2 * IN_DIM];
    int w = threadIdx.x >> 5, lane = threadIdx.x & 31;
    int n = blockIdx.x * WPB + w;
    if (n >= N_NODES) return;

    int beg = g_idx[n], end = g_idx[n + 1];
    float acc = 0.f;
    if (lane < IN_DIM) {
        #pragma unroll 4
        for (int e = beg; e < end; e++) {
            int src = g_csr_src[e];
            acc += __ldg(&x[src * IN_DIM + lane]);
        }
    }
    int degn = end - beg;
    float cnt = (float)(degn > 0 ? degn : 1);
    if (lane < IN_DIM) {
        sh[w][lane]          = acc / cnt;
        sh[w][IN_DIM + lane] = __ldg(&x[n * IN_DIM + lane]);
    }
    __syncwarp();

    int j = 4 * lane;
    float4 a = *(const float4*)&b[j];
    #pragma unroll
    for (int k = 0; k < IN_DIM; k++) {
        float  m  = sh[w][k];
        float  xx = sh[w][IN_DIM + k];
        float4 wl = *(const float4*)&Wl[k * HID + j];
        float4 wr = *(const float4*)&Wr[k * HID + j];
        a.x += m * wl.x + xx * wr.x;
        a.y += m * wl.y + xx * wr.y;
        a.z += m * wl.z + xx * wr.z;
        a.w += m * wl.w + xx * wr.w;
    }
    a.x = fmaxf(a.x, 0.f); a.y = fmaxf(a.y, 0.f);
    a.z = fmaxf(a.z, 0.f); a.w = fmaxf(a.w, 0.f);
    *(float4*)&g_h[(size_t)n * HID + j] = a;
}

// ---------------- layers 1/2: agg(h,128) + FC; FINAL adds sigmoid+hierarchy-max ----------------
template <bool FINAL>
__global__ void layerH_kernel(const float* __restrict__ Wl,
                              const float* __restrict__ Wr,
                              const float* __restrict__ b,
                              const int*   __restrict__ R,
                              float* __restrict__ final_out) {
    __shared__ float shm[WPB][HID];
    __shared__ float shh[WPB][HID];
    int w = threadIdx.x >> 5, lane = threadIdx.x & 31;
    int n = blockIdx.x * WPB + w;
    if (n >= N_NODES) return;

    const float* __restrict__ hin = FINAL ? (g_h + (size_t)N_NODES * HID) : g_h;

    int beg = g_idx[n], end = g_idx[n + 1];
    int j = 4 * lane;
    float4 acc = make_float4(0.f, 0.f, 0.f, 0.f);
    #pragma unroll 4
    for (int e = beg; e < end; e++) {
        int src = g_csr_src[e];
        float4 v = *(const float4*)&hin[(size_t)src * HID + j];
        acc.x += v.x; acc.y += v.y; acc.z += v.z; acc.w += v.w;
    }
    int degn = end - beg;
    float inv = 1.f / (float)(degn > 0 ? degn : 1);
    float4 hv = *(const float4*)&hin[(size_t)n * HID + j];
    *(float4*)&shm[w][j] = make_float4(acc.x * inv, acc.y * inv, acc.z * inv, acc.w * inv);
    *(float4*)&shh[w][j] = hv;
    __syncwarp();

    if (!FINAL) {
        float4 a = *(const float4*)&b[j];
        #pragma unroll 8
        for (int k = 0; k < HID; k++) {
            float  m  = shm[w][k];
            float  h  = shh[w][k];
            float4 wl = *(const float4*)&Wl[k * HID + j];
            float4 wr = *(const float4*)&Wr[k * HID + j];
            a.x += m * wl.x + h * wr.x;
            a.y += m * wl.y + h * wr.y;
            a.z += m * wl.z + h * wr.z;
            a.w += m * wl.w + h * wr.w;
        }
        a.x = fmaxf(a.x, 0.f); a.y = fmaxf(a.y, 0.f);
        a.z = fmaxf(a.z, 0.f); a.w = fmaxf(a.w, 0.f);
        *(float4*)&g_h[(size_t)N_NODES * HID + (size_t)n * HID + j] = a;
    } else {
        float a = 0.f;
        if (lane < OUT_DIM) {
            a = b[lane];
            #pragma unroll 8
            for (int k = 0; k < HID; k++) {
                a += shm[w][k] * Wl[k * OUT_DIM + lane]
                   + shh[w][k] * Wr[k * OUT_DIM + lane];
            }
            a = 1.f / (1.f + expf(-a));   // sigmoid
        }
        __syncwarp();
        if (lane < OUT_DIM) shm[w][lane] = a;   // reuse shared for sigmoid outputs
        __syncwarp();
        if (lane < OUT_DIM) {
            float mx = 0.f;
            #pragma unroll
            for (int jj = 0; jj < OUT_DIM; jj++) {
                if (R[lane * OUT_DIM + jj]) mx = fmaxf(mx, shm[w][jj]);
            }
            final_out[(size_t)n * OUT_DIM + lane] = mx;
        }
    }
}

// ---------------- launch ----------------
extern "C" void kernel_launch(void* const* d_in, const int* in_sizes, int n_in,
                              void* d_out, int out_size) {
    const float* x   = (const float*)d_in[0];
    const float* Wl0 = (const float*)d_in[1];
    const float* Wr0 = (const float*)d_in[2];
    const float* b0  = (const float*)d_in[3];
    const float* Wl1 = (const float*)d_in[4];
    const float* Wr1 = (const float*)d_in[5];
    const float* b1  = (const float*)d_in[6];
    const float* Wl2 = (const float*)d_in[7];
    const float* Wr2 = (const float*)d_in[8];
    const float* b2  = (const float*)d_in[9];
    const int*   ei  = (const int*)d_in[10];
    const int*   R   = (const int*)d_in[11];
    float* out = (float*)d_out;
    (void)in_sizes; (void)n_in; (void)out_size;

    zero_deg_kernel<<<(N_NODES + 255) / 256, 256>>>();
    hist_kernel<<<(N_EDGES + 255) / 256, 256>>>(ei);
    scan_kernel<<<1, 1024>>>();
    scatter_kernel<<<(N_EDGES + 255) / 256, 256>>>(ei);

    int nb = (N_NODES + WPB - 1) / WPB;
    layer0_kernel<<<nb, WPB * 32>>>(x, Wl0, Wr0, b0);
    layerH_kernel<false><<<nb, WPB * 32>>>(Wl1, Wr1, b1, (const int*)nullptr, (float*)nullptr);
    layerH_kernel<true ><<<nb, WPB * 32>>>(Wl2, Wr2, b2, R, out);
}

// round 4
// speedup vs baseline: 1.6158x; 1.6158x over previous
#include <cuda_runtime.h>

#define N_NODES 100000
#define N_EDGES 1600000
#define IN_DIM  12
#define HID     128
#define OUT_DIM 13
#define WPB     8      // warps (=nodes) per block for per-node kernels

// ---------------- scratch (static device globals; no allocation) ----------------
// idx layout: [0 .. N_NODES]   rowstart (N_NODES+1 ints)
//             [N_NODES+1 ..]   cursor   (N_NODES ints)
__device__ int   g_idx[2 * N_NODES + 1];
__device__ int   g_csr_src[N_EDGES];
__device__ float g_A[(size_t)N_NODES * HID];   // h (layer input/output)
__device__ float g_U[(size_t)N_NODES * HID];   // h @ Wl
__device__ float g_V[(size_t)N_NODES * HID];   // h @ Wr + b
__device__ float g_u2[(size_t)N_NODES * 16];   // h2 @ Wl2 (13, padded 16)
__device__ float g_v2[(size_t)N_NODES * 16];   // h2 @ Wr2 + b2

// ---------------- CSR construction ----------------
__global__ void zero_deg_kernel() {
    int i = blockIdx.x * blockDim.x + threadIdx.x;
    if (i < N_NODES) g_idx[i] = 0;
}

__global__ void hist_kernel(const int* __restrict__ ei) {
    int e = blockIdx.x * blockDim.x + threadIdx.x;
    if (e < N_EDGES) atomicAdd(&g_idx[__ldg(&ei[N_EDGES + e])], 1);  // dst
}

__global__ void scan_kernel() {
    const int T = 1024;
    int t = threadIdx.x;
    const int per = (N_NODES + T - 1) / T;
    int beg = t * per;
    int end = beg + per; if (end > N_NODES) end = N_NODES;
    if (beg > N_NODES) beg = N_NODES;

    int deg_local[98];
    int s = 0, cnt = end - beg;
    for (int i = 0; i < cnt; i++) { deg_local[i] = g_idx[beg + i]; s += deg_local[i]; }

    __shared__ int sh[T];
    sh[t] = s;
    __syncthreads();
    for (int off = 1; off < T; off <<= 1) {
        int v = (t >= off) ? sh[t - off] : 0;
        __syncthreads();
        sh[t] += v;
        __syncthreads();
    }
    int run = sh[t] - s;
    for (int i = 0; i < cnt; i++) {
        g_idx[beg + i]               = run;   // rowstart
        g_idx[N_NODES + 1 + beg + i] = run;   // cursor
        run += deg_local[i];
    }
    if (t == 0) g_idx[N_NODES] = sh[T - 1];
}

__global__ void scatter_kernel(const int* __restrict__ ei) {
    int e = blockIdx.x * blockDim.x + threadIdx.x;
    if (e < N_EDGES) {
        int dst = __ldg(&ei[N_EDGES + e]);
        int pos = atomicAdd(&g_idx[N_NODES + 1 + dst], 1);
        g_csr_src[pos] = __ldg(&ei[e]);
    }
}

// ---------------- layer 0: agg(x,12) + FC(12->128) + relu -> g_A ----------------
__global__ void layer0_kernel(const float* __restrict__ x,
                              const float* __restrict__ Wl,
                              const float* __restrict__ Wr,
                              const float* __restrict__ b) {
    __shared__ float sh[WPB][2 * IN_DIM];
    int w = threadIdx.x >> 5, lane = threadIdx.x & 31;
    int n = blockIdx.x * WPB + w;
    if (n >= N_NODES) return;

    int beg = g_idx[n], end = g_idx[n + 1];
    float acc = 0.f;
    if (lane < IN_DIM) {
        #pragma unroll 4
        for (int e = beg; e < end; e++) {
            int src = g_csr_src[e];
            acc += __ldg(&x[src * IN_DIM + lane]);
        }
    }
    int degn = end - beg;
    float cnt = (float)(degn > 0 ? degn : 1);
    if (lane < IN_DIM) {
        sh[w][lane]          = acc / cnt;
        sh[w][IN_DIM + lane] = __ldg(&x[n * IN_DIM + lane]);
    }
    __syncwarp();

    int j = 4 * lane;
    float4 a = *(const float4*)&b[j];
    #pragma unroll
    for (int k = 0; k < IN_DIM; k++) {
        float  m  = sh[w][k];
        float  xx = sh[w][IN_DIM + k];
        float4 wl = *(const float4*)&Wl[k * HID + j];
        float4 wr = *(const float4*)&Wr[k * HID + j];
        a.x += m * wl.x + xx * wr.x;
        a.y += m * wl.y + xx * wr.y;
        a.z += m * wl.z + xx * wr.z;
        a.w += m * wl.w + xx * wr.w;
    }
    a.x = fmaxf(a.x, 0.f); a.y = fmaxf(a.y, 0.f);
    a.z = fmaxf(a.z, 0.f); a.w = fmaxf(a.w, 0.f);
    *(float4*)&g_A[(size_t)n * HID + j] = a;
}

// ---------------- blocked SGEMM: U = A@Wl (y=0), V = A@Wr + b (y=1) ----------------
// 256 threads, 64(M) x 128(N) tile, K streamed in chunks of 16.
__global__ void sgemm_kernel(const float* __restrict__ Wl,
                             const float* __restrict__ Wr,
                             const float* __restrict__ bias) {
    const float* __restrict__ B = blockIdx.y ? Wr : Wl;
    float* __restrict__ C = blockIdx.y ? g_V : g_U;

    __shared__ float As[16][65];    // transposed, stride 65 -> conflict-free stores
    __shared__ float Bs[16][128];

    int tid = threadIdx.x;
    int w = tid >> 5, lane = tid & 31;
    int m_base = blockIdx.x * 64;

    float acc[8][4];
    #pragma unroll
    for (int i = 0; i < 8; i++)
        acc[i][0] = acc[i][1] = acc[i][2] = acc[i][3] = 0.f;

    int a_row = tid >> 2;            // 0..63
    int a_k   = (tid & 3) * 4;       // 0,4,8,12
    int b_k   = tid >> 4;            // 0..15
    int b_n   = (tid & 15) * 8;      // 0..120
    int a_grow = m_base + a_row;
    if (a_grow >= N_NODES) a_grow = N_NODES - 1;
    const float* __restrict__ Arow = g_A + (size_t)a_grow * HID;

    for (int k0 = 0; k0 < HID; k0 += 16) {
        float4 av  = *(const float4*)&Arow[k0 + a_k];
        float4 bv0 = *(const float4*)&B[(k0 + b_k) * HID + b_n];
        float4 bv1 = *(const float4*)&B[(k0 + b_k) * HID + b_n + 4];
        __syncthreads();
        As[a_k + 0][a_row] = av.x;
        As[a_k + 1][a_row] = av.y;
        As[a_k + 2][a_row] = av.z;
        As[a_k + 3][a_row] = av.w;
        *(float4*)&Bs[b_k][b_n]     = bv0;
        *(float4*)&Bs[b_k][b_n + 4] = bv1;
        __syncthreads();
        #pragma unroll
        for (int kk = 0; kk < 16; kk++) {
            float4 b4 = *(const float4*)&Bs[kk][lane * 4];
            float a0[8];
            #pragma unroll
            for (int i = 0; i < 8; i++) a0[i] = As[kk][w * 8 + i];   // broadcast
            #pragma unroll
            for (int i = 0; i < 8; i++) {
                acc[i][0] += a0[i] * b4.x;
                acc[i][1] += a0[i] * b4.y;
                acc[i][2] += a0[i] * b4.z;
                acc[i][3] += a0[i] * b4.w;
            }
        }
    }

    float4 bb = make_float4(0.f, 0.f, 0.f, 0.f);
    if (blockIdx.y) bb = *(const float4*)&bias[lane * 4];
    #pragma unroll
    for (int i = 0; i < 8; i++) {
        int m = m_base + w * 8 + i;
        if (m < N_NODES) {
            float4 r = make_float4(acc[i][0] + bb.x, acc[i][1] + bb.y,
                                   acc[i][2] + bb.z, acc[i][3] + bb.w);
            *(float4*)&C[(size_t)m * HID + lane * 4] = r;
        }
    }
}

// ---------------- agg1: h2 = relu(mean(U[nbrs]) + V[n]) -> g_A ----------------
__global__ void agg_kernel() {
    int w = threadIdx.x >> 5, lane = threadIdx.x & 31;
    int n = blockIdx.x * WPB + w;
    if (n >= N_NODES) return;

    int beg = g_idx[n], end = g_idx[n + 1];
    int j = 4 * lane;
    float4 acc = make_float4(0.f, 0.f, 0.f, 0.f);
    #pragma unroll 4
    for (int e = beg; e < end; e++) {
        int src = g_csr_src[e];
        float4 v = *(const float4*)&g_U[(size_t)src * HID + j];
        acc.x += v.x; acc.y += v.y; acc.z += v.z; acc.w += v.w;
    }
    int degn = end - beg;
    float inv = 1.f / (float)(degn > 0 ? degn : 1);
    float4 vv = *(const float4*)&g_V[(size_t)n * HID + j];
    float4 r;
    r.x = fmaxf(acc.x * inv + vv.x, 0.f);
    r.y = fmaxf(acc.y * inv + vv.y, 0.f);
    r.z = fmaxf(acc.z * inv + vv.z, 0.f);
    r.w = fmaxf(acc.w * inv + vv.w, 0.f);
    *(float4*)&g_A[(size_t)n * HID + j] = r;
}

// ---------------- gemm2: u2 = h2@Wl2 ; v2 = h2@Wr2 + b2 (13 cols each) ----------------
__global__ void gemm2_kernel(const float* __restrict__ Wl2,
                             const float* __restrict__ Wr2,
                             const float* __restrict__ b2) {
    __shared__ float W2s[HID][26];      // cols 0..12 = Wl2, 13..25 = Wr2
    __shared__ float h_sh[WPB][HID];
    int tid = threadIdx.x;
    int w = tid >> 5, lane = tid & 31;

    for (int i = tid; i < HID * OUT_DIM; i += WPB * 32) {
        int k = i / OUT_DIM, c = i % OUT_DIM;
        W2s[k][c]           = Wl2[i];
        W2s[k][OUT_DIM + c] = Wr2[i];
    }
    __syncthreads();

    int n = blockIdx.x * WPB + w;
    if (n >= N_NODES) return;

    int j = 4 * lane;
    *(float4*)&h_sh[w][j] = *(const float4*)&g_A[(size_t)n * HID + j];
    __syncwarp();

    if (lane < 2 * OUT_DIM) {
        float acc = 0.f;
        #pragma unroll 8
        for (int k = 0; k < HID; k++)
            acc += h_sh[w][k] * W2s[k][lane];
        if (lane < OUT_DIM) {
            g_u2[(size_t)n * 16 + lane] = acc;
        } else {
            g_v2[(size_t)n * 16 + (lane - OUT_DIM)] = acc + b2[lane - OUT_DIM];
        }
    }
}

// ---------------- final: out = hiermax(sigmoid(mean(u2[nbrs]) + v2[n])) ----------------
__global__ void aggF_kernel(const int* __restrict__ R, float* __restrict__ out) {
    __shared__ float s[WPB][OUT_DIM];
    int w = threadIdx.x >> 5, lane = threadIdx.x & 31;
    int n = blockIdx.x * WPB + w;
    if (n >= N_NODES) return;

    int beg = g_idx[n], end = g_idx[n + 1];
    float acc = 0.f;
    if (lane < OUT_DIM) {
        #pragma unroll 4
        for (int e = beg; e < end; e++) {
            int src = g_csr_src[e];
            acc += g_u2[(size_t)src * 16 + lane];
        }
    }
    int degn = end - beg;
    float inv = 1.f / (float)(degn > 0 ? degn : 1);
    if (lane < OUT_DIM) {
        float z = acc * inv + g_v2[(size_t)n * 16 + lane];
        s[w][lane] = 1.f / (1.f + expf(-z));
    }
    __syncwarp();
    if (lane < OUT_DIM) {
        float mx = 0.f;
        #pragma unroll
        for (int jj = 0; jj < OUT_DIM; jj++) {
            if (__ldg(&R[lane * OUT_DIM + jj])) mx = fmaxf(mx, s[w][jj]);
        }
        out[(size_t)n * OUT_DIM + lane] = mx;
    }
}

// ---------------- launch ----------------
extern "C" void kernel_launch(void* const* d_in, const int* in_sizes, int n_in,
                              void* d_out, int out_size) {
    const float* x   = (const float*)d_in[0];
    const float* Wl0 = (const float*)d_in[1];
    const float* Wr0 = (const float*)d_in[2];
    const float* b0  = (const float*)d_in[3];
    const float* Wl1 = (const float*)d_in[4];
    const float* Wr1 = (const float*)d_in[5];
    const float* b1  = (const float*)d_in[6];
    const float* Wl2 = (const float*)d_in[7];
    const float* Wr2 = (const float*)d_in[8];
    const float* b2  = (const float*)d_in[9];
    const int*   ei  = (const int*)d_in[10];
    const int*   R   = (const int*)d_in[11];
    float* out = (float*)d_out;
    (void)in_sizes; (void)n_in; (void)out_size;

    zero_deg_kernel<<<(N_NODES + 255) / 256, 256>>>();
    hist_kernel<<<(N_EDGES + 255) / 256, 256>>>(ei);
    scan_kernel<<<1, 1024>>>();
    scatter_kernel<<<(N_EDGES + 255) / 256, 256>>>(ei);

    int nb = (N_NODES + WPB - 1) / WPB;
    layer0_kernel<<<nb, WPB * 32>>>(x, Wl0, Wr0, b0);

    dim3 gg((N_NODES + 63) / 64, 2);
    sgemm_kernel<<<gg, 256>>>(Wl1, Wr1, b1);
    agg_kernel<<<nb, WPB * 32>>>();

    gemm2_kernel<<<nb, WPB * 32>>>(Wl2, Wr2, b2);
    aggF_kernel<<<nb, WPB * 32>>>(R, out);
}

// round 5
// speedup vs baseline: 1.7603x; 1.0894x over previous
#include <cuda_runtime.h>
#include <cuda_bf16.h>

#define N_NODES 100000
#define N_EDGES 1600000
#define IN_DIM  12
#define HID     128
#define OUT_DIM 13
#define WPB     8      // warps (=nodes) per block for per-node kernels

// ---------------- scratch (static device globals; no allocation) ----------------
__device__ int      g_idx[2 * N_NODES + 1];        // rowstart | cursor
__device__ int      g_csr_src[N_EDGES];
__device__ float    g_A[(size_t)N_NODES * HID];    // h2 (fp32, written by agg)
__device__ float    g_U[(size_t)N_NODES * HID];    // h1 @ Wl1
__device__ float    g_V[(size_t)N_NODES * HID];    // h1 @ Wr1 + b1
__device__ unsigned g_Ah[(size_t)N_NODES * 64];    // h1 packed bf16x2 (hi)
__device__ unsigned g_Al[(size_t)N_NODES * 64];    // h1 packed bf16x2 (lo)
__device__ unsigned g_Wth[2 * 128 * 64];           // W^T packed bf16x2 hi: [m][n][kpair]
__device__ unsigned g_Wtl[2 * 128 * 64];           // lo
__device__ float    g_u2[(size_t)N_NODES * 16];    // h2 @ Wl2 (13, pad 16)
__device__ float    g_v2[(size_t)N_NODES * 16];    // h2 @ Wr2 + b2

// ---------------- helpers ----------------
__device__ __forceinline__ unsigned pack_hi(float x, float y) {
    __nv_bfloat16 bx = __float2bfloat16(x);
    __nv_bfloat16 by = __float2bfloat16(y);
    return ((unsigned)__bfloat16_as_ushort(by) << 16) | __bfloat16_as_ushort(bx);
}
__device__ __forceinline__ unsigned pack_lo(float x, float y) {
    float rx = x - __bfloat162float(__float2bfloat16(x));
    float ry = y - __bfloat162float(__float2bfloat16(y));
    __nv_bfloat16 bx = __float2bfloat16(rx);
    __nv_bfloat16 by = __float2bfloat16(ry);
    return ((unsigned)__bfloat16_as_ushort(by) << 16) | __bfloat16_as_ushort(bx);
}

#define MMA_BF16(d, a, b)                                                        \
    asm volatile(                                                                \
        "mma.sync.aligned.m16n8k16.row.col.f32.bf16.bf16.f32 "                   \
        "{%0,%1,%2,%3}, {%4,%5,%6,%7}, {%8,%9}, {%0,%1,%2,%3};\n"                \
        : "+f"((d)[0]), "+f"((d)[1]), "+f"((d)[2]), "+f"((d)[3])                 \
        : "r"((a)[0]), "r"((a)[1]), "r"((a)[2]), "r"((a)[3]),                    \
          "r"((b)[0]), "r"((b)[1]))

// ---------------- CSR construction ----------------
__global__ void zero_deg_kernel() {
    int i = blockIdx.x * blockDim.x + threadIdx.x;
    if (i < N_NODES) g_idx[i] = 0;
}

__global__ void hist_kernel(const int* __restrict__ ei) {
    int e = blockIdx.x * blockDim.x + threadIdx.x;
    if (e < N_EDGES) atomicAdd(&g_idx[__ldg(&ei[N_EDGES + e])], 1);
}

__global__ void scan_kernel() {
    const int T = 1024;
    int t = threadIdx.x;
    const int per = (N_NODES + T - 1) / T;
    int beg = t * per;
    int end = beg + per; if (end > N_NODES) end = N_NODES;
    if (beg > N_NODES) beg = N_NODES;

    int deg_local[98];
    int s = 0, cnt = end - beg;
    for (int i = 0; i < cnt; i++) { deg_local[i] = g_idx[beg + i]; s += deg_local[i]; }

    __shared__ int sh[T];
    sh[t] = s;
    __syncthreads();
    for (int off = 1; off < T; off <<= 1) {
        int v = (t >= off) ? sh[t - off] : 0;
        __syncthreads();
        sh[t] += v;
        __syncthreads();
    }
    int run = sh[t] - s;
    for (int i = 0; i < cnt; i++) {
        g_idx[beg + i]               = run;
        g_idx[N_NODES + 1 + beg + i] = run;
        run += deg_local[i];
    }
    if (t == 0) g_idx[N_NODES] = sh[T - 1];
}

__global__ void scatter_kernel(const int* __restrict__ ei) {
    int e = blockIdx.x * blockDim.x + threadIdx.x;
    if (e < N_EDGES) {
        int dst = __ldg(&ei[N_EDGES + e]);
        int pos = atomicAdd(&g_idx[N_NODES + 1 + dst], 1);
        g_csr_src[pos] = __ldg(&ei[e]);
    }
}

// ---------------- layer 0: agg(x,12) + FC(12->128) + relu -> packed bf16 h1 ----------------
__global__ void layer0_kernel(const float* __restrict__ x,
                              const float* __restrict__ Wl,
                              const float* __restrict__ Wr,
                              const float* __restrict__ b) {
    __shared__ float sh[WPB][2 * IN_DIM];
    int w = threadIdx.x >> 5, lane = threadIdx.x & 31;
    int n = blockIdx.x * WPB + w;
    if (n >= N_NODES) return;

    int beg = g_idx[n], end = g_idx[n + 1];
    float acc = 0.f;
    if (lane < IN_DIM) {
        #pragma unroll 4
        for (int e = beg; e < end; e++) {
            int src = g_csr_src[e];
            acc += __ldg(&x[src * IN_DIM + lane]);
        }
    }
    int degn = end - beg;
    float cnt = (float)(degn > 0 ? degn : 1);
    if (lane < IN_DIM) {
        sh[w][lane]          = acc / cnt;
        sh[w][IN_DIM + lane] = __ldg(&x[n * IN_DIM + lane]);
    }
    __syncwarp();

    int j = 4 * lane;
    float4 a = *(const float4*)&b[j];
    #pragma unroll
    for (int k = 0; k < IN_DIM; k++) {
        float  m  = sh[w][k];
        float  xx = sh[w][IN_DIM + k];
        float4 wl = *(const float4*)&Wl[k * HID + j];
        float4 wr = *(const float4*)&Wr[k * HID + j];
        a.x += m * wl.x + xx * wr.x;
        a.y += m * wl.y + xx * wr.y;
        a.z += m * wl.z + xx * wr.z;
        a.w += m * wl.w + xx * wr.w;
    }
    a.x = fmaxf(a.x, 0.f); a.y = fmaxf(a.y, 0.f);
    a.z = fmaxf(a.z, 0.f); a.w = fmaxf(a.w, 0.f);

    size_t base = (size_t)n * 64 + 2 * lane;
    g_Ah[base]     = pack_hi(a.x, a.y);
    g_Ah[base + 1] = pack_hi(a.z, a.w);
    g_Al[base]     = pack_lo(a.x, a.y);
    g_Al[base + 1] = pack_lo(a.z, a.w);
}

// ---------------- prep: W1 -> transposed split-bf16 [n][kpair] ----------------
__global__ void prep_w_kernel(const float* __restrict__ Wl,
                              const float* __restrict__ Wr) {
    int m = blockIdx.x >> 7;          // 0=Wl, 1=Wr
    int n = blockIdx.x & 127;
    int c = threadIdx.x;              // 0..63 (k pair)
    const float* __restrict__ W = m ? Wr : Wl;
    float w0 = W[(2 * c)     * HID + n];
    float w1 = W[(2 * c + 1) * HID + n];
    int idx = m * (128 * 64) + n * 64 + c;
    g_Wth[idx] = pack_hi(w0, w1);
    g_Wtl[idx] = pack_lo(w0, w1);
}

// ---------------- tensor-core SGEMM: U = h1@Wl1 (y=0), V = h1@Wr1 + b1 (y=1) ----------------
// 256 threads (8 warps = 2x4), 64(M) x 128(N) block tile, K chunked by 32 floats.
// Shared stride 20 u32 => conflict-free 8x4 lane fragment loads.
__global__ void sgemm_tc_kernel(const float* __restrict__ bias) {
    __shared__ unsigned As_h[64 * 20], As_l[64 * 20];
    __shared__ unsigned Bs_h[128 * 20], Bs_l[128 * 20];

    int tid = threadIdx.x, lane = tid & 31, wid = tid >> 5;
    int warp_m = wid >> 2, warp_n = wid & 3;
    int m_base = blockIdx.x * 64;
    int sel = blockIdx.y;
    const unsigned* __restrict__ Wt_h = g_Wth + sel * (128 * 64);
    const unsigned* __restrict__ Wt_l = g_Wtl + sel * (128 * 64);

    float acc[2][4][4];
    #pragma unroll
    for (int i = 0; i < 2; i++)
        #pragma unroll
        for (int jj = 0; jj < 4; jj++)
            acc[i][jj][0] = acc[i][jj][1] = acc[i][jj][2] = acc[i][jj][3] = 0.f;

    int ar = tid >> 2, ac4 = (tid & 3) * 4;             // A loader: 64 rows x 16 u32
    int arow = m_base + ar; if (arow >= N_NODES) arow = N_NODES - 1;
    int bn = tid >> 1, bc8 = (tid & 1) * 8;             // B loader: 128 rows x 16 u32

    for (int k0 = 0; k0 < 64; k0 += 16) {               // u32 units (32 floats/chunk)
        uint4 ah = *(const uint4*)&g_Ah[(size_t)arow * 64 + k0 + ac4];
        uint4 al = *(const uint4*)&g_Al[(size_t)arow * 64 + k0 + ac4];
        uint4 bh0 = *(const uint4*)&Wt_h[bn * 64 + k0 + bc8];
        uint4 bh1 = *(const uint4*)&Wt_h[bn * 64 + k0 + bc8 + 4];
        uint4 bl0 = *(const uint4*)&Wt_l[bn * 64 + k0 + bc8];
        uint4 bl1 = *(const uint4*)&Wt_l[bn * 64 + k0 + bc8 + 4];
        __syncthreads();
        *(uint4*)&As_h[ar * 20 + ac4] = ah;
        *(uint4*)&As_l[ar * 20 + ac4] = al;
        *(uint4*)&Bs_h[bn * 20 + bc8]     = bh0;
        *(uint4*)&Bs_h[bn * 20 + bc8 + 4] = bh1;
        *(uint4*)&Bs_l[bn * 20 + bc8]     = bl0;
        *(uint4*)&Bs_l[bn * 20 + bc8 + 4] = bl1;
        __syncthreads();

        #pragma unroll
        for (int ks = 0; ks < 2; ks++) {
            int cb = ks * 8 + (lane & 3);
            unsigned a_h[2][4], a_l[2][4];
            #pragma unroll
            for (int tm = 0; tm < 2; tm++) {
                int r0 = (warp_m * 32 + tm * 16 + (lane >> 2)) * 20 + cb;
                a_h[tm][0] = As_h[r0];            a_h[tm][1] = As_h[r0 + 8 * 20];
                a_h[tm][2] = As_h[r0 + 4];        a_h[tm][3] = As_h[r0 + 8 * 20 + 4];
                a_l[tm][0] = As_l[r0];            a_l[tm][1] = As_l[r0 + 8 * 20];
                a_l[tm][2] = As_l[r0 + 4];        a_l[tm][3] = As_l[r0 + 8 * 20 + 4];
            }
            unsigned b_h[4][2], b_l[4][2];
            #pragma unroll
            for (int tn = 0; tn < 4; tn++) {
                int q = (warp_n * 32 + tn * 8 + (lane >> 2)) * 20 + cb;
                b_h[tn][0] = Bs_h[q]; b_h[tn][1] = Bs_h[q + 4];
                b_l[tn][0] = Bs_l[q]; b_l[tn][1] = Bs_l[q + 4];
            }
            #pragma unroll
            for (int tm = 0; tm < 2; tm++)
                #pragma unroll
                for (int tn = 0; tn < 4; tn++) {
                    MMA_BF16(acc[tm][tn], a_h[tm], b_h[tn]);
                    MMA_BF16(acc[tm][tn], a_h[tm], b_l[tn]);
                    MMA_BF16(acc[tm][tn], a_l[tm], b_h[tn]);
                }
        }
    }

    float* __restrict__ C = sel ? g_V : g_U;
    #pragma unroll
    for (int tn = 0; tn < 4; tn++) {
        int col = warp_n * 32 + tn * 8 + 2 * (lane & 3);
        float bx = 0.f, by = 0.f;
        if (sel) { bx = __ldg(&bias[col]); by = __ldg(&bias[col + 1]); }
        #pragma unroll
        for (int tm = 0; tm < 2; tm++) {
            int row0 = m_base + warp_m * 32 + tm * 16 + (lane >> 2);
            if (row0 < N_NODES) {
                float2 r = make_float2(acc[tm][tn][0] + bx, acc[tm][tn][1] + by);
                *(float2*)&C[(size_t)row0 * HID + col] = r;
            }
            int row1 = row0 + 8;
            if (row1 < N_NODES) {
                float2 r = make_float2(acc[tm][tn][2] + bx, acc[tm][tn][3] + by);
                *(float2*)&C[(size_t)row1 * HID + col] = r;
            }
        }
    }
}

// ---------------- agg1: h2 = relu(mean(U[nbrs]) + V[n]) -> g_A ----------------
__global__ void agg_kernel() {
    int w = threadIdx.x >> 5, lane = threadIdx.x & 31;
    int n = blockIdx.x * WPB + w;
    if (n >= N_NODES) return;

    int beg = g_idx[n], end = g_idx[n + 1];
    int j = 4 * lane;
    float4 acc = make_float4(0.f, 0.f, 0.f, 0.f);
    #pragma unroll 4
    for (int e = beg; e < end; e++) {
        int src = g_csr_src[e];
        float4 v = *(const float4*)&g_U[(size_t)src * HID + j];
        acc.x += v.x; acc.y += v.y; acc.z += v.z; acc.w += v.w;
    }
    int degn = end - beg;
    float inv = 1.f / (float)(degn > 0 ? degn : 1);
    float4 vv = *(const float4*)&g_V[(size_t)n * HID + j];
    float4 r;
    r.x = fmaxf(acc.x * inv + vv.x, 0.f);
    r.y = fmaxf(acc.y * inv + vv.y, 0.f);
    r.z = fmaxf(acc.z * inv + vv.z, 0.f);
    r.w = fmaxf(acc.w * inv + vv.w, 0.f);
    *(float4*)&g_A[(size_t)n * HID + j] = r;
}

// ---------------- gemm2: u2 = h2@Wl2 ; v2 = h2@Wr2 + b2 ----------------
__global__ void gemm2_kernel(const float* __restrict__ Wl2,
                             const float* __restrict__ Wr2,
                             const float* __restrict__ b2) {
    __shared__ float W2s[HID][26];
    __shared__ float h_sh[WPB][HID];
    int tid = threadIdx.x;
    int w = tid >> 5, lane = tid & 31;

    for (int i = tid; i < HID * OUT_DIM; i += WPB * 32) {
        int k = i / OUT_DIM, c = i % OUT_DIM;
        W2s[k][c]           = Wl2[i];
        W2s[k][OUT_DIM + c] = Wr2[i];
    }
    __syncthreads();

    int n = blockIdx.x * WPB + w;
    if (n >= N_NODES) return;

    int j = 4 * lane;
    *(float4*)&h_sh[w][j] = *(const float4*)&g_A[(size_t)n * HID + j];
    __syncwarp();

    if (lane < 2 * OUT_DIM) {
        float acc = 0.f;
        #pragma unroll 8
        for (int k = 0; k < HID; k++)
            acc += h_sh[w][k] * W2s[k][lane];
        if (lane < OUT_DIM) {
            g_u2[(size_t)n * 16 + lane] = acc;
        } else {
            g_v2[(size_t)n * 16 + (lane - OUT_DIM)] = acc + b2[lane - OUT_DIM];
        }
    }
}

// ---------------- final: out = hiermax(sigmoid(mean(u2[nbrs]) + v2[n])) ----------------
__global__ void aggF_kernel(const int* __restrict__ R, float* __restrict__ out) {
    __shared__ float s[WPB][OUT_DIM];
    int w = threadIdx.x >> 5, lane = threadIdx.x & 31;
    int n = blockIdx.x * WPB + w;
    if (n >= N_NODES) return;

    int beg = g_idx[n], end = g_idx[n + 1];
    float acc = 0.f;
    if (lane < OUT_DIM) {
        #pragma unroll 4
        for (int e = beg; e < end; e++) {
            int src = g_csr_src[e];
            acc += g_u2[(size_t)src * 16 + lane];
        }
    }
    int degn = end - beg;
    float inv = 1.f / (float)(degn > 0 ? degn : 1);
    if (lane < OUT_DIM) {
        float z = acc * inv + g_v2[(size_t)n * 16 + lane];
        s[w][lane] = 1.f / (1.f + expf(-z));
    }
    __syncwarp();
    if (lane < OUT_DIM) {
        float mx = 0.f;
        #pragma unroll
        for (int jj = 0; jj < OUT_DIM; jj++) {
            if (__ldg(&R[lane * OUT_DIM + jj])) mx = fmaxf(mx, s[w][jj]);
        }
        out[(size_t)n * OUT_DIM + lane] = mx;
    }
}

// ---------------- launch ----------------
extern "C" void kernel_launch(void* const* d_in, const int* in_sizes, int n_in,
                              void* d_out, int out_size) {
    const float* x   = (const float*)d_in[0];
    const float* Wl0 = (const float*)d_in[1];
    const float* Wr0 = (const float*)d_in[2];
    const float* b0  = (const float*)d_in[3];
    const float* Wl1 = (const float*)d_in[4];
    const float* Wr1 = (const float*)d_in[5];
    const float* b1  = (const float*)d_in[6];
    const float* Wl2 = (const float*)d_in[7];
    const float* Wr2 = (const float*)d_in[8];
    const float* b2  = (const float*)d_in[9];
    const int*   ei  = (const int*)d_in[10];
    const int*   R   = (const int*)d_in[11];
    float* out = (float*)d_out;
    (void)in_sizes; (void)n_in; (void)out_size;

    zero_deg_kernel<<<(N_NODES + 255) / 256, 256>>>();
    hist_kernel<<<(N_EDGES + 255) / 256, 256>>>(ei);
    scan_kernel<<<1, 1024>>>();
    scatter_kernel<<<(N_EDGES + 255) / 256, 256>>>(ei);

    prep_w_kernel<<<256, 64>>>(Wl1, Wr1);

    int nb = (N_NODES + WPB - 1) / WPB;
    layer0_kernel<<<nb, WPB * 32>>>(x, Wl0, Wr0, b0);

    dim3 gg((N_NODES + 63) / 64, 2);
    sgemm_tc_kernel<<<gg, 256>>>(b1);
    agg_kernel<<<nb, WPB * 32>>>();

    gemm2_kernel<<<nb, WPB * 32>>>(Wl2, Wr2, b2);
    aggF_kernel<<<nb, WPB * 32>>>(R, out);
}

// round 6
// speedup vs baseline: 2.4608x; 1.3980x over previous
#include <cuda_runtime.h>
#include <cuda_bf16.h>

#define N_NODES 100000
#define N_EDGES 1600000
#define IN_DIM  12
#define HID     128
#define OUT_DIM 13
#define WPB     8      // warps per block (layer0)
#define WPB_F   16     // warps per block (fused agg kernels)
#define SCAN_B  391    // ceil(N_NODES/256)

// ---------------- scratch (static device globals; no allocation) ----------------
__device__ int      g_idx[2 * N_NODES + 1];        // rowstart | cursor
__device__ int      g_bsum[512];                   // scan block sums
__device__ int      g_csr_src[N_EDGES];
__device__ float    g_U[(size_t)N_NODES * HID];    // h1 @ Wl1
__device__ float    g_V[(size_t)N_NODES * HID];    // h1 @ Wr1 + b1
__device__ unsigned g_Ah[(size_t)N_NODES * 64];    // h1 packed bf16x2 (hi)
__device__ unsigned g_Al[(size_t)N_NODES * 64];    // h1 packed bf16x2 (lo)
__device__ unsigned g_Wth[2 * 128 * 64];           // W1^T packed bf16x2 hi: [m][n][kpair]
__device__ unsigned g_Wtl[2 * 128 * 64];           // lo
__device__ float    g_u2[(size_t)N_NODES * 16];    // h2 @ Wl2 (13, pad 16)
__device__ float    g_v2[(size_t)N_NODES * 16];    // h2 @ Wr2 + b2

// ---------------- helpers ----------------
__device__ __forceinline__ unsigned pack_hi(float x, float y) {
    __nv_bfloat16 bx = __float2bfloat16(x);
    __nv_bfloat16 by = __float2bfloat16(y);
    return ((unsigned)__bfloat16_as_ushort(by) << 16) | __bfloat16_as_ushort(bx);
}
__device__ __forceinline__ unsigned pack_lo(float x, float y) {
    float rx = x - __bfloat162float(__float2bfloat16(x));
    float ry = y - __bfloat162float(__float2bfloat16(y));
    __nv_bfloat16 bx = __float2bfloat16(rx);
    __nv_bfloat16 by = __float2bfloat16(ry);
    return ((unsigned)__bfloat16_as_ushort(by) << 16) | __bfloat16_as_ushort(bx);
}

#define MMA_BF16(d, a, b)                                                        \
    asm volatile(                                                                \
        "mma.sync.aligned.m16n8k16.row.col.f32.bf16.bf16.f32 "                   \
        "{%0,%1,%2,%3}, {%4,%5,%6,%7}, {%8,%9}, {%0,%1,%2,%3};\n"                \
        : "+f"((d)[0]), "+f"((d)[1]), "+f"((d)[2]), "+f"((d)[3])                 \
        : "r"((a)[0]), "r"((a)[1]), "r"((a)[2]), "r"((a)[3]),                    \
          "r"((b)[0]), "r"((b)[1]))

// ---------------- CSR construction ----------------
__global__ void zero_deg_kernel() {
    int i = blockIdx.x * blockDim.x + threadIdx.x;
    if (i < N_NODES) g_idx[i] = 0;
}

__global__ void hist_kernel(const int* __restrict__ ei) {
    int e = blockIdx.x * blockDim.x + threadIdx.x;
    if (e < N_EDGES) atomicAdd(&g_idx[__ldg(&ei[N_EDGES + e])], 1);
}

// 3-phase scan: per-block local exclusive scan, block-sum scan, offset add.
__global__ void scan1_kernel() {
    __shared__ int sh[256];
    int t = threadIdx.x, i = blockIdx.x * 256 + t;
    int d = (i < N_NODES) ? g_idx[i] : 0;
    sh[t] = d;
    __syncthreads();
    #pragma unroll
    for (int off = 1; off < 256; off <<= 1) {
        int v = (t >= off) ? sh[t - off] : 0;
        __syncthreads();
        sh[t] += v;
        __syncthreads();
    }
    if (i < N_NODES) g_idx[i] = sh[t] - d;          // exclusive within block
    if (t == 255) g_bsum[blockIdx.x] = sh[255];     // block total
}

__global__ void scan2_kernel() {
    __shared__ int sh[512];
    int t = threadIdx.x;
    int v = (t < SCAN_B) ? g_bsum[t] : 0;
    sh[t] = v;
    __syncthreads();
    #pragma unroll
    for (int off = 1; off < 512; off <<= 1) {
        int u = (t >= off) ? sh[t - off] : 0;
        __syncthreads();
        sh[t] += u;
        __syncthreads();
    }
    if (t < SCAN_B) g_bsum[t] = sh[t] - v;          // exclusive block offsets
    if (t == 0) g_idx[N_NODES] = N_EDGES;
}

__global__ void scan3_kernel() {
    int t = threadIdx.x, i = blockIdx.x * 256 + t;
    if (i < N_NODES) {
        int r = g_idx[i] + g_bsum[blockIdx.x];
        g_idx[i]               = r;   // rowstart
        g_idx[N_NODES + 1 + i] = r;   // cursor
    }
}

__global__ void scatter_kernel(const int* __restrict__ ei) {
    int e = blockIdx.x * blockDim.x + threadIdx.x;
    if (e < N_EDGES) {
        int dst = __ldg(&ei[N_EDGES + e]);
        int pos = atomicAdd(&g_idx[N_NODES + 1 + dst], 1);
        g_csr_src[pos] = __ldg(&ei[e]);
    }
}

// ---------------- layer 0: agg(x,12) + FC(12->128) + relu -> packed bf16 h1 ----------------
__global__ void layer0_kernel(const float* __restrict__ x,
                              const float* __restrict__ Wl,
                              const float* __restrict__ Wr,
                              const float* __restrict__ b) {
    __shared__ float sh[WPB][2 * IN_DIM];
    int w = threadIdx.x >> 5, lane = threadIdx.x & 31;
    int n = blockIdx.x * WPB + w;
    if (n >= N_NODES) return;

    int beg = g_idx[n], end = g_idx[n + 1];
    float acc = 0.f;
    if (lane < IN_DIM) {
        #pragma unroll 4
        for (int e = beg; e < end; e++) {
            int src = g_csr_src[e];
            acc += __ldg(&x[src * IN_DIM + lane]);
        }
    }
    int degn = end - beg;
    float cnt = (float)(degn > 0 ? degn : 1);
    if (lane < IN_DIM) {
        sh[w][lane]          = acc / cnt;
        sh[w][IN_DIM + lane] = __ldg(&x[n * IN_DIM + lane]);
    }
    __syncwarp();

    int j = 4 * lane;
    float4 a = *(const float4*)&b[j];
    #pragma unroll
    for (int k = 0; k < IN_DIM; k++) {
        float  m  = sh[w][k];
        float  xx = sh[w][IN_DIM + k];
        float4 wl = *(const float4*)&Wl[k * HID + j];
        float4 wr = *(const float4*)&Wr[k * HID + j];
        a.x += m * wl.x + xx * wr.x;
        a.y += m * wl.y + xx * wr.y;
        a.z += m * wl.z + xx * wr.z;
        a.w += m * wl.w + xx * wr.w;
    }
    a.x = fmaxf(a.x, 0.f); a.y = fmaxf(a.y, 0.f);
    a.z = fmaxf(a.z, 0.f); a.w = fmaxf(a.w, 0.f);

    size_t base = (size_t)n * 64 + 2 * lane;
    g_Ah[base]     = pack_hi(a.x, a.y);
    g_Ah[base + 1] = pack_hi(a.z, a.w);
    g_Al[base]     = pack_lo(a.x, a.y);
    g_Al[base + 1] = pack_lo(a.z, a.w);
}

// ---------------- prep: W1 -> transposed split-bf16 [n][kpair] ----------------
__global__ void prep_w_kernel(const float* __restrict__ Wl,
                              const float* __restrict__ Wr) {
    int m = blockIdx.x >> 7;
    int n = blockIdx.x & 127;
    int c = threadIdx.x;              // 0..63 (k pair)
    const float* __restrict__ W = m ? Wr : Wl;
    float w0 = W[(2 * c)     * HID + n];
    float w1 = W[(2 * c + 1) * HID + n];
    int idx = m * (128 * 64) + n * 64 + c;
    g_Wth[idx] = pack_hi(w0, w1);
    g_Wtl[idx] = pack_lo(w0, w1);
}

// ---------------- tensor-core SGEMM: U = h1@Wl1 (y=0), V = h1@Wr1 + b1 (y=1) ----------------
__global__ void sgemm_tc_kernel(const float* __restrict__ bias) {
    __shared__ unsigned As_h[64 * 20], As_l[64 * 20];
    __shared__ unsigned Bs_h[128 * 20], Bs_l[128 * 20];

    int tid = threadIdx.x, lane = tid & 31, wid = tid >> 5;
    int warp_m = wid >> 2, warp_n = wid & 3;
    int m_base = blockIdx.x * 64;
    int sel = blockIdx.y;
    const unsigned* __restrict__ Wt_h = g_Wth + sel * (128 * 64);
    const unsigned* __restrict__ Wt_l = g_Wtl + sel * (128 * 64);

    float acc[2][4][4];
    #pragma unroll
    for (int i = 0; i < 2; i++)
        #pragma unroll
        for (int jj = 0; jj < 4; jj++)
            acc[i][jj][0] = acc[i][jj][1] = acc[i][jj][2] = acc[i][jj][3] = 0.f;

    int ar = tid >> 2, ac4 = (tid & 3) * 4;
    int arow = m_base + ar; if (arow >= N_NODES) arow = N_NODES - 1;
    int bn = tid >> 1, bc8 = (tid & 1) * 8;

    for (int k0 = 0; k0 < 64; k0 += 16) {
        uint4 ah = *(const uint4*)&g_Ah[(size_t)arow * 64 + k0 + ac4];
        uint4 al = *(const uint4*)&g_Al[(size_t)arow * 64 + k0 + ac4];
        uint4 bh0 = *(const uint4*)&Wt_h[bn * 64 + k0 + bc8];
        uint4 bh1 = *(const uint4*)&Wt_h[bn * 64 + k0 + bc8 + 4];
        uint4 bl0 = *(const uint4*)&Wt_l[bn * 64 + k0 + bc8];
        uint4 bl1 = *(const uint4*)&Wt_l[bn * 64 + k0 + bc8 + 4];
        __syncthreads();
        *(uint4*)&As_h[ar * 20 + ac4] = ah;
        *(uint4*)&As_l[ar * 20 + ac4] = al;
        *(uint4*)&Bs_h[bn * 20 + bc8]     = bh0;
        *(uint4*)&Bs_h[bn * 20 + bc8 + 4] = bh1;
        *(uint4*)&Bs_l[bn * 20 + bc8]     = bl0;
        *(uint4*)&Bs_l[bn * 20 + bc8 + 4] = bl1;
        __syncthreads();

        #pragma unroll
        for (int ks = 0; ks < 2; ks++) {
            int cb = ks * 8 + (lane & 3);
            unsigned a_h[2][4], a_l[2][4];
            #pragma unroll
            for (int tm = 0; tm < 2; tm++) {
                int r0 = (warp_m * 32 + tm * 16 + (lane >> 2)) * 20 + cb;
                a_h[tm][0] = As_h[r0];            a_h[tm][1] = As_h[r0 + 8 * 20];
                a_h[tm][2] = As_h[r0 + 4];        a_h[tm][3] = As_h[r0 + 8 * 20 + 4];
                a_l[tm][0] = As_l[r0];            a_l[tm][1] = As_l[r0 + 8 * 20];
                a_l[tm][2] = As_l[r0 + 4];        a_l[tm][3] = As_l[r0 + 8 * 20 + 4];
            }
            unsigned b_h[4][2], b_l[4][2];
            #pragma unroll
            for (int tn = 0; tn < 4; tn++) {
                int q = (warp_n * 32 + tn * 8 + (lane >> 2)) * 20 + cb;
                b_h[tn][0] = Bs_h[q]; b_h[tn][1] = Bs_h[q + 4];
                b_l[tn][0] = Bs_l[q]; b_l[tn][1] = Bs_l[q + 4];
            }
            #pragma unroll
            for (int tm = 0; tm < 2; tm++)
                #pragma unroll
                for (int tn = 0; tn < 4; tn++) {
                    MMA_BF16(acc[tm][tn], a_h[tm], b_h[tn]);
                    MMA_BF16(acc[tm][tn], a_h[tm], b_l[tn]);
                    MMA_BF16(acc[tm][tn], a_l[tm], b_h[tn]);
                }
        }
    }

    float* __restrict__ C = sel ? g_V : g_U;
    #pragma unroll
    for (int tn = 0; tn < 4; tn++) {
        int col = warp_n * 32 + tn * 8 + 2 * (lane & 3);
        float bx = 0.f, by = 0.f;
        if (sel) { bx = __ldg(&bias[col]); by = __ldg(&bias[col + 1]); }
        #pragma unroll
        for (int tm = 0; tm < 2; tm++) {
            int row0 = m_base + warp_m * 32 + tm * 16 + (lane >> 2);
            if (row0 < N_NODES) {
                float2 r = make_float2(acc[tm][tn][0] + bx, acc[tm][tn][1] + by);
                *(float2*)&C[(size_t)row0 * HID + col] = r;
            }
            int row1 = row0 + 8;
            if (row1 < N_NODES) {
                float2 r = make_float2(acc[tm][tn][2] + bx, acc[tm][tn][3] + by);
                *(float2*)&C[(size_t)row1 * HID + col] = r;
            }
        }
    }
}

// ---------------- fused: h2 = relu(mean(U[nbrs]) + V[n]); u2 = h2@Wl2; v2 = h2@Wr2 + b2 ----------------
__global__ void aggGemm2_kernel(const float* __restrict__ Wl2,
                                const float* __restrict__ Wr2,
                                const float* __restrict__ b2) {
    __shared__ float W2s[HID][26];            // cols 0..12 = Wl2, 13..25 = Wr2
    __shared__ float h_sh[WPB_F][HID];
    int tid = threadIdx.x;
    int w = tid >> 5, lane = tid & 31;

    for (int i = tid; i < HID * OUT_DIM; i += WPB_F * 32) {
        int k = i / OUT_DIM, c = i % OUT_DIM;
        W2s[k][c]           = Wl2[i];
        W2s[k][OUT_DIM + c] = Wr2[i];
    }
    __syncthreads();

    int n = blockIdx.x * WPB_F + w;
    if (n >= N_NODES) return;

    int beg = g_idx[n], end = g_idx[n + 1];
    int j = 4 * lane;
    float4 acc = make_float4(0.f, 0.f, 0.f, 0.f);
    #pragma unroll 4
    for (int e = beg; e < end; e++) {
        int src = g_csr_src[e];
        float4 v = *(const float4*)&g_U[(size_t)src * HID + j];
        acc.x += v.x; acc.y += v.y; acc.z += v.z; acc.w += v.w;
    }
    int degn = end - beg;
    float inv = 1.f / (float)(degn > 0 ? degn : 1);
    float4 vv = *(const float4*)&g_V[(size_t)n * HID + j];
    float4 r;
    r.x = fmaxf(acc.x * inv + vv.x, 0.f);
    r.y = fmaxf(acc.y * inv + vv.y, 0.f);
    r.z = fmaxf(acc.z * inv + vv.z, 0.f);
    r.w = fmaxf(acc.w * inv + vv.w, 0.f);
    *(float4*)&h_sh[w][j] = r;
    __syncwarp();

    if (lane < 2 * OUT_DIM) {
        float a = 0.f;
        #pragma unroll 8
        for (int k = 0; k < HID; k++)
            a += h_sh[w][k] * W2s[k][lane];
        if (lane < OUT_DIM) {
            g_u2[(size_t)n * 16 + lane] = a;
        } else {
            g_v2[(size_t)n * 16 + (lane - OUT_DIM)] = a + b2[lane - OUT_DIM];
        }
    }
}

// ---------------- final: out = hiermax(sigmoid(mean(u2[nbrs]) + v2[n])) ----------------
__global__ void aggF_kernel(const int* __restrict__ R, float* __restrict__ out) {
    __shared__ float s[WPB_F][OUT_DIM];
    int w = threadIdx.x >> 5, lane = threadIdx.x & 31;
    int n = blockIdx.x * WPB_F + w;
    if (n >= N_NODES) return;

    int beg = g_idx[n], end = g_idx[n + 1];
    float acc = 0.f;
    if (lane < OUT_DIM) {
        #pragma unroll 4
        for (int e = beg; e < end; e++) {
            int src = g_csr_src[e];
            acc += g_u2[(size_t)src * 16 + lane];
        }
    }
    int degn = end - beg;
    float inv = 1.f / (float)(degn > 0 ? degn : 1);
    if (lane < OUT_DIM) {
        float z = acc * inv + g_v2[(size_t)n * 16 + lane];
        s[w][lane] = 1.f / (1.f + expf(-z));
    }
    __syncwarp();
    if (lane < OUT_DIM) {
        float mx = 0.f;
        #pragma unroll
        for (int jj = 0; jj < OUT_DIM; jj++) {
            if (__ldg(&R[lane * OUT_DIM + jj])) mx = fmaxf(mx, s[w][jj]);
        }
        out[(size_t)n * OUT_DIM + lane] = mx;
    }
}

// ---------------- launch ----------------
extern "C" void kernel_launch(void* const* d_in, const int* in_sizes, int n_in,
                              void* d_out, int out_size) {
    const float* x   = (const float*)d_in[0];
    const float* Wl0 = (const float*)d_in[1];
    const float* Wr0 = (const float*)d_in[2];
    const float* b0  = (const float*)d_in[3];
    const float* Wl1 = (const float*)d_in[4];
    const float* Wr1 = (const float*)d_in[5];
    const float* b1  = (const float*)d_in[6];
    const float* Wl2 = (const float*)d_in[7];
    const float* Wr2 = (const float*)d_in[8];
    const float* b2  = (const float*)d_in[9];
    const int*   ei  = (const int*)d_in[10];
    const int*   R   = (const int*)d_in[11];
    float* out = (float*)d_out;
    (void)in_sizes; (void)n_in; (void)out_size;

    zero_deg_kernel<<<(N_NODES + 255) / 256, 256>>>();
    hist_kernel<<<(N_EDGES + 255) / 256, 256>>>(ei);
    scan1_kernel<<<SCAN_B, 256>>>();
    scan2_kernel<<<1, 512>>>();
    scan3_kernel<<<SCAN_B, 256>>>();
    scatter_kernel<<<(N_EDGES + 255) / 256, 256>>>(ei);

    prep_w_kernel<<<256, 64>>>(Wl1, Wr1);

    int nb = (N_NODES + WPB - 1) / WPB;
    layer0_kernel<<<nb, WPB * 32>>>(x, Wl0, Wr0, b0);

    dim3 gg((N_NODES + 63) / 64, 2);
    sgemm_tc_kernel<<<gg, 256>>>(b1);

    int nbf = (N_NODES + WPB_F - 1) / WPB_F;
    aggGemm2_kernel<<<nbf, WPB_F * 32>>>(Wl2, Wr2, b2);
    aggF_kernel<<<nbf, WPB_F * 32>>>(R, out);
}

// round 8
// speedup vs baseline: 2.5684x; 1.0437x over previous
#include <cuda_runtime.h>
#include <cuda_bf16.h>
#include <cuda_fp16.h>

#define N_NODES 100000
#define N_EDGES 1600000
#define IN_DIM  12
#define HID     128
#define OUT_DIM 13
#define WPB     8      // warps per block (layer0)
#define WPB_F   16     // warps per block (fused agg kernels)
#define SCAN_B  391    // ceil(N_NODES/256)

// ---------------- scratch (static device globals; no allocation) ----------------
__device__ int      g_idx[2 * N_NODES + 1];        // rowstart | cursor
__device__ int      g_bsum[512];                   // scan block sums
__device__ int      g_csr_src[N_EDGES];
__device__ unsigned g_U16[(size_t)N_NODES * 64];   // h1 @ Wl1, packed half2
__device__ float    g_V[(size_t)N_NODES * HID];    // h1 @ Wr1 + b1 (fp32)
__device__ unsigned g_Ah[(size_t)N_NODES * 64];    // h1 packed bf16x2 (hi)
__device__ unsigned g_Al[(size_t)N_NODES * 64];    // h1 packed bf16x2 (lo)
__device__ unsigned g_Wth[2 * 128 * 64];           // W1^T packed bf16x2 hi: [m][n][kpair]
__device__ unsigned g_Wtl[2 * 128 * 64];           // lo
__device__ float    g_u2[(size_t)N_NODES * 16];    // h2 @ Wl2 (13, pad 16)
__device__ float    g_v2[(size_t)N_NODES * 16];    // h2 @ Wr2 + b2

// ---------------- helpers ----------------
__device__ __forceinline__ unsigned pack_hi(float x, float y) {
    __nv_bfloat16 bx = __float2bfloat16(x);
    __nv_bfloat16 by = __float2bfloat16(y);
    return ((unsigned)__bfloat16_as_ushort(by) << 16) | __bfloat16_as_ushort(bx);
}
__device__ __forceinline__ unsigned pack_lo(float x, float y) {
    float rx = x - __bfloat162float(__float2bfloat16(x));
    float ry = y - __bfloat162float(__float2bfloat16(y));
    __nv_bfloat16 bx = __float2bfloat16(rx);
    __nv_bfloat16 by = __float2bfloat16(ry);
    return ((unsigned)__bfloat16_as_ushort(by) << 16) | __bfloat16_as_ushort(bx);
}

#define MMA_BF16(d, a, b)                                                        \
    asm volatile(                                                                \
        "mma.sync.aligned.m16n8k16.row.col.f32.bf16.bf16.f32 "                   \
        "{%0,%1,%2,%3}, {%4,%5,%6,%7}, {%8,%9}, {%0,%1,%2,%3};\n"                \
        : "+f"((d)[0]), "+f"((d)[1]), "+f"((d)[2]), "+f"((d)[3])                 \
        : "r"((a)[0]), "r"((a)[1]), "r"((a)[2]), "r"((a)[3]),                    \
          "r"((b)[0]), "r"((b)[1]))

// ---------------- CSR construction ----------------
__global__ void zero_deg_kernel() {
    int i = blockIdx.x * blockDim.x + threadIdx.x;
    if (i < N_NODES) g_idx[i] = 0;
}

__global__ void hist_kernel(const int* __restrict__ ei) {
    int e = blockIdx.x * blockDim.x + threadIdx.x;
    if (e < N_EDGES) atomicAdd(&g_idx[__ldg(&ei[N_EDGES + e])], 1);
}

__global__ void scan1_kernel() {
    __shared__ int sh[256];
    int t = threadIdx.x, i = blockIdx.x * 256 + t;
    int d = (i < N_NODES) ? g_idx[i] : 0;
    sh[t] = d;
    __syncthreads();
    #pragma unroll
    for (int off = 1; off < 256; off <<= 1) {
        int v = (t >= off) ? sh[t - off] : 0;
        __syncthreads();
        sh[t] += v;
        __syncthreads();
    }
    if (i < N_NODES) g_idx[i] = sh[t] - d;
    if (t == 255) g_bsum[blockIdx.x] = sh[255];
}

__global__ void scan2_kernel() {
    __shared__ int sh[512];
    int t = threadIdx.x;
    int v = (t < SCAN_B) ? g_bsum[t] : 0;
    sh[t] = v;
    __syncthreads();
    #pragma unroll
    for (int off = 1; off < 512; off <<= 1) {
        int u = (t >= off) ? sh[t - off] : 0;
        __syncthreads();
        sh[t] += u;
        __syncthreads();
    }
    if (t < SCAN_B) g_bsum[t] = sh[t] - v;
    if (t == 0) g_idx[N_NODES] = N_EDGES;
}

__global__ void scan3_kernel() {
    int t = threadIdx.x, i = blockIdx.x * 256 + t;
    if (i < N_NODES) {
        int r = g_idx[i] + g_bsum[blockIdx.x];
        g_idx[i]               = r;   // rowstart
        g_idx[N_NODES + 1 + i] = r;   // cursor
    }
}

__global__ void scatter_kernel(const int* __restrict__ ei) {
    int e = blockIdx.x * blockDim.x + threadIdx.x;
    if (e < N_EDGES) {
        int dst = __ldg(&ei[N_EDGES + e]);
        int pos = atomicAdd(&g_idx[N_NODES + 1 + dst], 1);
        g_csr_src[pos] = __ldg(&ei[e]);
    }
}

// ---------------- layer 0: agg(x,12) + FC(12->128) + relu -> packed bf16 h1 ----------------
__global__ void layer0_kernel(const float* __restrict__ x,
                              const float* __restrict__ Wl,
                              const float* __restrict__ Wr,
                              const float* __restrict__ b) {
    __shared__ float sh[WPB][2 * IN_DIM];
    int w = threadIdx.x >> 5, lane = threadIdx.x & 31;
    int n = blockIdx.x * WPB + w;
    if (n >= N_NODES) return;

    int beg = g_idx[n], end = g_idx[n + 1];
    float acc = 0.f;
    if (lane < IN_DIM) {
        #pragma unroll 4
        for (int e = beg; e < end; e++) {
            int src = g_csr_src[e];
            acc += __ldg(&x[src * IN_DIM + lane]);
        }
    }
    int degn = end - beg;
    float cnt = (float)(degn > 0 ? degn : 1);
    if (lane < IN_DIM) {
        sh[w][lane]          = acc / cnt;
        sh[w][IN_DIM + lane] = __ldg(&x[n * IN_DIM + lane]);
    }
    __syncwarp();

    int j = 4 * lane;
    float4 a = *(const float4*)&b[j];
    #pragma unroll
    for (int k = 0; k < IN_DIM; k++) {
        float  m  = sh[w][k];
        float  xx = sh[w][IN_DIM + k];
        float4 wl = *(const float4*)&Wl[k * HID + j];
        float4 wr = *(const float4*)&Wr[k * HID + j];
        a.x += m * wl.x + xx * wr.x;
        a.y += m * wl.y + xx * wr.y;
        a.z += m * wl.z + xx * wr.z;
        a.w += m * wl.w + xx * wr.w;
    }
    a.x = fmaxf(a.x, 0.f); a.y = fmaxf(a.y, 0.f);
    a.z = fmaxf(a.z, 0.f); a.w = fmaxf(a.w, 0.f);

    size_t base = (size_t)n * 64 + 2 * lane;
    g_Ah[base]     = pack_hi(a.x, a.y);
    g_Ah[base + 1] = pack_hi(a.z, a.w);
    g_Al[base]     = pack_lo(a.x, a.y);
    g_Al[base + 1] = pack_lo(a.z, a.w);
}

// ---------------- prep: W1 -> transposed split-bf16 [n][kpair] ----------------
__global__ void prep_w_kernel(const float* __restrict__ Wl,
                              const float* __restrict__ Wr) {
    int m = blockIdx.x >> 7;
    int n = blockIdx.x & 127;
    int c = threadIdx.x;              // 0..63 (k pair)
    const float* __restrict__ W = m ? Wr : Wl;
    float w0 = W[(2 * c)     * HID + n];
    float w1 = W[(2 * c + 1) * HID + n];
    int idx = m * (128 * 64) + n * 64 + c;
    g_Wth[idx] = pack_hi(w0, w1);
    g_Wtl[idx] = pack_lo(w0, w1);
}

// ---------------- tensor-core SGEMM: U(half) = h1@Wl1 (y=0), V = h1@Wr1 + b1 (y=1) ----------------
__global__ void sgemm_tc_kernel(const float* __restrict__ bias) {
    __shared__ unsigned As_h[64 * 20], As_l[64 * 20];
    __shared__ unsigned Bs_h[128 * 20], Bs_l[128 * 20];

    int tid = threadIdx.x, lane = tid & 31, wid = tid >> 5;
    int warp_m = wid >> 2, warp_n = wid & 3;
    int m_base = blockIdx.x * 64;
    int sel = blockIdx.y;
    const unsigned* __restrict__ Wt_h = g_Wth + sel * (128 * 64);
    const unsigned* __restrict__ Wt_l = g_Wtl + sel * (128 * 64);

    float acc[2][4][4];
    #pragma unroll
    for (int i = 0; i < 2; i++)
        #pragma unroll
        for (int jj = 0; jj < 4; jj++)
            acc[i][jj][0] = acc[i][jj][1] = acc[i][jj][2] = acc[i][jj][3] = 0.f;

    int ar = tid >> 2, ac4 = (tid & 3) * 4;
    int arow = m_base + ar; if (arow >= N_NODES) arow = N_NODES - 1;
    int bn = tid >> 1, bc8 = (tid & 1) * 8;

    for (int k0 = 0; k0 < 64; k0 += 16) {
        uint4 ah = *(const uint4*)&g_Ah[(size_t)arow * 64 + k0 + ac4];
        uint4 al = *(const uint4*)&g_Al[(size_t)arow * 64 + k0 + ac4];
        uint4 bh0 = *(const uint4*)&Wt_h[bn * 64 + k0 + bc8];
        uint4 bh1 = *(const uint4*)&Wt_h[bn * 64 + k0 + bc8 + 4];
        uint4 bl0 = *(const uint4*)&Wt_l[bn * 64 + k0 + bc8];
        uint4 bl1 = *(const uint4*)&Wt_l[bn * 64 + k0 + bc8 + 4];
        __syncthreads();
        *(uint4*)&As_h[ar * 20 + ac4] = ah;
        *(uint4*)&As_l[ar * 20 + ac4] = al;
        *(uint4*)&Bs_h[bn * 20 + bc8]     = bh0;
        *(uint4*)&Bs_h[bn * 20 + bc8 + 4] = bh1;
        *(uint4*)&Bs_l[bn * 20 + bc8]     = bl0;
        *(uint4*)&Bs_l[bn * 20 + bc8 + 4] = bl1;
        __syncthreads();

        #pragma unroll
        for (int ks = 0; ks < 2; ks++) {
            int cb = ks * 8 + (lane & 3);
            unsigned a_h[2][4], a_l[2][4];
            #pragma unroll
            for (int tm = 0; tm < 2; tm++) {
                int r0 = (warp_m * 32 + tm * 16 + (lane >> 2)) * 20 + cb;
                a_h[tm][0] = As_h[r0];            a_h[tm][1] = As_h[r0 + 8 * 20];
                a_h[tm][2] = As_h[r0 + 4];        a_h[tm][3] = As_h[r0 + 8 * 20 + 4];
                a_l[tm][0] = As_l[r0];            a_l[tm][1] = As_l[r0 + 8 * 20];
                a_l[tm][2] = As_l[r0 + 4];        a_l[tm][3] = As_l[r0 + 8 * 20 + 4];
            }
            unsigned b_h[4][2], b_l[4][2];
            #pragma unroll
            for (int tn = 0; tn < 4; tn++) {
                int q = (warp_n * 32 + tn * 8 + (lane >> 2)) * 20 + cb;
                b_h[tn][0] = Bs_h[q]; b_h[tn][1] = Bs_h[q + 4];
                b_l[tn][0] = Bs_l[q]; b_l[tn][1] = Bs_l[q + 4];
            }
            #pragma unroll
            for (int tm = 0; tm < 2; tm++)
                #pragma unroll
                for (int tn = 0; tn < 4; tn++) {
                    MMA_BF16(acc[tm][tn], a_h[tm], b_h[tn]);
                    MMA_BF16(acc[tm][tn], a_h[tm], b_l[tn]);
                    MMA_BF16(acc[tm][tn], a_l[tm], b_h[tn]);
                }
        }
    }

    #pragma unroll
    for (int tn = 0; tn < 4; tn++) {
        int col = warp_n * 32 + tn * 8 + 2 * (lane & 3);
        if (sel) {
            float bx = __ldg(&bias[col]), by = __ldg(&bias[col + 1]);
            #pragma unroll
            for (int tm = 0; tm < 2; tm++) {
                int row0 = m_base + warp_m * 32 + tm * 16 + (lane >> 2);
                if (row0 < N_NODES) {
                    float2 r = make_float2(acc[tm][tn][0] + bx, acc[tm][tn][1] + by);
                    *(float2*)&g_V[(size_t)row0 * HID + col] = r;
                }
                int row1 = row0 + 8;
                if (row1 < N_NODES) {
                    float2 r = make_float2(acc[tm][tn][2] + bx, acc[tm][tn][3] + by);
                    *(float2*)&g_V[(size_t)row1 * HID + col] = r;
                }
            }
        } else {
            #pragma unroll
            for (int tm = 0; tm < 2; tm++) {
                int row0 = m_base + warp_m * 32 + tm * 16 + (lane >> 2);
                if (row0 < N_NODES) {
                    __half2 h = __floats2half2_rn(acc[tm][tn][0], acc[tm][tn][1]);
                    g_U16[(size_t)row0 * 64 + col / 2] = *(unsigned*)&h;
                }
                int row1 = row0 + 8;
                if (row1 < N_NODES) {
                    __half2 h = __floats2half2_rn(acc[tm][tn][2], acc[tm][tn][3]);
                    g_U16[(size_t)row1 * 64 + col / 2] = *(unsigned*)&h;
                }
            }
        }
    }
}

// ---------------- fused: h2 = relu(mean(U[nbrs]) + V[n]); u2 = h2@Wl2; v2 = h2@Wr2 + b2 ----------------
__global__ void aggGemm2_kernel(const float* __restrict__ Wl2,
                                const float* __restrict__ Wr2,
                                const float* __restrict__ b2) {
    __shared__ float W2s[HID][26];            // cols 0..12 = Wl2, 13..25 = Wr2
    __shared__ float h_sh[WPB_F][HID];
    int tid = threadIdx.x;
    int w = tid >> 5, lane = tid & 31;

    for (int i = tid; i < HID * OUT_DIM; i += WPB_F * 32) {
        int k = i / OUT_DIM, c = i % OUT_DIM;
        W2s[k][c]           = Wl2[i];
        W2s[k][OUT_DIM + c] = Wr2[i];
    }
    __syncthreads();

    int n = blockIdx.x * WPB_F + w;
    if (n >= N_NODES) return;

    int beg = g_idx[n], end = g_idx[n + 1];
    int jh = 2 * lane;                        // half2 index (4 floats per lane)
    float4 acc = make_float4(0.f, 0.f, 0.f, 0.f);
    #pragma unroll 4
    for (int e = beg; e < end; e++) {
        int src = g_csr_src[e];
        uint2 u = *(const uint2*)&g_U16[(size_t)src * 64 + jh];
        float2 f0 = __half22float2(*(const __half2*)&u.x);
        float2 f1 = __half22float2(*(const __half2*)&u.y);
        acc.x += f0.x; acc.y += f0.y; acc.z += f1.x; acc.w += f1.y;
    }
    int degn = end - beg;
    float inv = 1.f / (float)(degn > 0 ? degn : 1);
    int j = 4 * lane;
    float4 vv = *(const float4*)&g_V[(size_t)n * HID + j];
    float4 r;
    r.x = fmaxf(acc.x * inv + vv.x, 0.f);
    r.y = fmaxf(acc.y * inv + vv.y, 0.f);
    r.z = fmaxf(acc.z * inv + vv.z, 0.f);
    r.w = fmaxf(acc.w * inv + vv.w, 0.f);
    *(float4*)&h_sh[w][j] = r;
    __syncwarp();

    if (lane < 2 * OUT_DIM) {
        float a = 0.f;
        #pragma unroll 8
        for (int k = 0; k < HID; k++)
            a += h_sh[w][k] * W2s[k][lane];
        if (lane < OUT_DIM) {
            g_u2[(size_t)n * 16 + lane] = a;
        } else {
            g_v2[(size_t)n * 16 + (lane - OUT_DIM)] = a + b2[lane - OUT_DIM];
        }
    }
}

// ---------------- final: out = hiermax(sigmoid(mean(u2[nbrs]) + v2[n])) ----------------
__global__ void aggF_kernel(const int* __restrict__ R, float* __restrict__ out) {
    __shared__ float s[WPB_F][OUT_DIM];
    int w = threadIdx.x >> 5, lane = threadIdx.x & 31;
    int n = blockIdx.x * WPB_F + w;
    if (n >= N_NODES) return;

    int beg = g_idx[n], end = g_idx[n + 1];
    float acc = 0.f;
    if (lane < OUT_DIM) {
        #pragma unroll 4
        for (int e = beg; e < end; e++) {
            int src = g_csr_src[e];
            acc += g_u2[(size_t)src * 16 + lane];
        }
    }
    int degn = end - beg;
    float inv = 1.f / (float)(degn > 0 ? degn : 1);
    if (lane < OUT_DIM) {
        float z = acc * inv + g_v2[(size_t)n * 16 + lane];
        s[w][lane] = 1.f / (1.f + expf(-z));
    }
    __syncwarp();
    if (lane < OUT_DIM) {
        float mx = 0.f;
        #pragma unroll
        for (int jj = 0; jj < OUT_DIM; jj++) {
            if (__ldg(&R[lane * OUT_DIM + jj])) mx = fmaxf(mx, s[w][jj]);
        }
        out[(size_t)n * OUT_DIM + lane] = mx;
    }
}

// ---------------- launch ----------------
extern "C" void kernel_launch(void* const* d_in, const int* in_sizes, int n_in,
                              void* d_out, int out_size) {
    const float* x   = (const float*)d_in[0];
    const float* Wl0 = (const float*)d_in[1];
    const float* Wr0 = (const float*)d_in[2];
    const float* b0  = (const float*)d_in[3];
    const float* Wl1 = (const float*)d_in[4];
    const float* Wr1 = (const float*)d_in[5];
    const float* b1  = (const float*)d_in[6];
    const float* Wl2 = (const float*)d_in[7];
    const float* Wr2 = (const float*)d_in[8];
    const float* b2  = (const float*)d_in[9];
    const int*   ei  = (const int*)d_in[10];
    const int*   R   = (const int*)d_in[11];
    float* out = (float*)d_out;
    (void)in_sizes; (void)n_in; (void)out_size;

    zero_deg_kernel<<<(N_NODES + 255) / 256, 256>>>();
    hist_kernel<<<(N_EDGES + 255) / 256, 256>>>(ei);
    scan1_kernel<<<SCAN_B, 256>>>();
    scan2_kernel<<<1, 512>>>();
    scan3_kernel<<<SCAN_B, 256>>>();
    scatter_kernel<<<(N_EDGES + 255) / 256, 256>>>(ei);

    prep_w_kernel<<<256, 64>>>(Wl1, Wr1);

    int nb = (N_NODES + WPB - 1) / WPB;
    layer0_kernel<<<nb, WPB * 32>>>(x, Wl0, Wr0, b0);

    dim3 gg((N_NODES + 63) / 64, 2);
    sgemm_tc_kernel<<<gg, 256>>>(b1);

    int nbf = (N_NODES + WPB_F - 1) / WPB_F;
    aggGemm2_kernel<<<nbf, WPB_F * 32>>>(Wl2, Wr2, b2);
    aggF_kernel<<<nbf, WPB_F * 32>>>(R, out);
}